// round 11
// baseline (speedup 1.0000x reference)
#include <cuda_runtime.h>
#include <cuda_fp16.h>
#include <math.h>
#include <stdint.h>

#define B_   2
#define H_   8
#define NQ_  2048
#define NK_  2048
#define DM_  512
#define HD_  64
#define EXP2C 0.18033688011112042f   /* 0.125 * log2(e) */

#define SH2 36   // half2 words per 64-half row; 36%32==4 -> conflict-free frags
#define XF  40   // f32 words per 32-f32 row (32+8 pad); conflict-free float2 frags
#define WS  20   // uint32 words per 32-half W row (16+4 pad); 20*lq+lr banks distinct

// Scratch (allocation-free rule: __device__ globals)
__device__ __half g_Q[B_*H_*NQ_*HD_];
__device__ __half g_K[B_*H_*NK_*HD_];
__device__ __half g_V[B_*H_*NK_*HD_];
__device__ __half g_Wh[3*DM_*DM_];
__device__ float  g_diag[B_*H_*NK_];

// ---------------------------------------------------------------------------
// helpers
// ---------------------------------------------------------------------------
__device__ __forceinline__ float fast_ex2(float x) {
    float y;
    asm("ex2.approx.ftz.f32 %0, %1;" : "=f"(y) : "f"(x));
    return y;
}
__device__ __forceinline__ uint32_t f2h2(float lo, float hi) {
    __half2 h = __floats2half2_rn(lo, hi);
    return *reinterpret_cast<uint32_t*>(&h);
}
__device__ __forceinline__ uint32_t ldsf2h(const float* p) {
    float2 v = *(const float2*)p;
    return f2h2(v.x, v.y);
}
__device__ __forceinline__ void mma_f16(float c[4], const uint32_t a[4],
                                        uint32_t b0, uint32_t b1) {
    asm volatile(
        "mma.sync.aligned.m16n8k16.row.col.f32.f16.f16.f32 "
        "{%0,%1,%2,%3}, {%4,%5,%6,%7}, {%8,%9}, {%0,%1,%2,%3};\n"
        : "+f"(c[0]), "+f"(c[1]), "+f"(c[2]), "+f"(c[3])
        : "r"(a[0]), "r"(a[1]), "r"(a[2]), "r"(a[3]), "r"(b0), "r"(b1));
}
__device__ __forceinline__ void ldsm_x4_t(uint32_t r[4], uint32_t addr) {
    asm volatile(
        "ldmatrix.sync.aligned.m8n8.x4.trans.shared.b16 {%0,%1,%2,%3}, [%4];"
        : "=r"(r[0]), "=r"(r[1]), "=r"(r[2]), "=r"(r[3]) : "r"(addr));
}
__device__ __forceinline__ uint32_t smem_u32(const void* p) {
    uint32_t a;
    asm("{ .reg .u64 t; cvta.to.shared.u64 t, %1; cvt.u32.u64 %0, t; }"
        : "=r"(a) : "l"(p));
    return a;
}
#define CPASYNC16(dst, src) \
    asm volatile("cp.async.cg.shared.global [%0], [%1], 16;" :: "r"(dst), "l"(src))
#define CPCOMMIT() asm volatile("cp.async.commit_group;" ::: "memory")
#define CPWAIT0()  asm volatile("cp.async.wait_group 0;"  ::: "memory")

// ---------------------------------------------------------------------------
// W fp32 -> fp16 pre-convert: g_Wh[z][n][k], k contiguous.
// grid 768 x 256; one float4 per thread.
// ---------------------------------------------------------------------------
__global__ void wcvt_kernel(const float* __restrict__ Wq,
                            const float* __restrict__ Wk,
                            const float* __restrict__ Wv)
{
    int idx = blockIdx.x * 256 + threadIdx.x;        // 0 .. 196607 (float4)
    const float* src = (idx < 65536) ? Wq : (idx < 131072 ? Wk : Wv);
    float4 w = *(const float4*)(src + (size_t)(idx & 65535) * 4);
    uint2 o;
    o.x = f2h2(w.x, w.y);
    o.y = f2h2(w.z, w.w);
    *(uint2*)(g_Wh + (size_t)idx * 4) = o;
}

// ---------------------------------------------------------------------------
// Projection, fp16 m16n8k16, cp.async double-buffered, 512 threads.
// Tile: M=128 x N=128, K-chunk 32 (16 chunks).
// X staged f32 (stride XF); W staged fp16 from g_Wh (stride WS words) ->
// B-frags are raw LDS.32, no CVT in the hot loop.
// smem (f32 words): X[2]@0/5120, W[2]@10240/12800  -> 61440 B.
// W staging: 512 thr x 16B = 8 KB = full 128 rows x 32 halfs.  (R10 bug:
// only 256 thr -> half the chunk staged -> NaN. Fixed.)
// grid (DM/128, B*N/128, 3); block 512 (16 warps: m=warp&7, n=warp>>3).
// ---------------------------------------------------------------------------
#define PROJ_SMEM (15360 * 4)

__global__ __launch_bounds__(512) void proj_kernel(
    const float* __restrict__ q, const float* __restrict__ k,
    const float* __restrict__ v,
    const float* __restrict__ bq, const float* __restrict__ bk,
    const float* __restrict__ bv)
{
    extern __shared__ float smf[];
    uint32_t* smu = (uint32_t*)smf;
    const uint32_t sb = smem_u32(smf);

    const float *X, *bias;
    const __half* Wh;
    __half* outp;
    if (blockIdx.z == 0)      { X = q; bias = bq; Wh = g_Wh;              outp = g_Q; }
    else if (blockIdx.z == 1) { X = k; bias = bk; Wh = g_Wh + DM_*DM_;    outp = g_K; }
    else                      { X = v; bias = bv; Wh = g_Wh + 2*DM_*DM_;  outp = g_V; }

    const int tid  = threadIdx.x;
    const int lane = tid & 31, warp = tid >> 5;
    const int lq = lane >> 2, lr = lane & 3;
    const int m0 = (warp & 7) * 16;
    const int n0 = (warp >> 3) * 64;
    const int row0 = blockIdx.y * 128;
    const int col0 = blockIdx.x * 128;

    // X staging: 512 thr x 16B x 2 it = 16 KB (128 rows x 32 f32)
    const int sr = tid >> 3;           // 0..63, r = sr + it*64
    const int sc = (tid & 7) << 2;     // f32 col 0,4,..28
    // W staging: 512 thr x 16B = 8 KB (128 rows x 32 halfs)
    const int wr = tid >> 2;           // 0..127
    const int wg = (tid & 3) << 3;     // half col 0,8,16,24

    float acc[8][4];
    #pragma unroll
    for (int j = 0; j < 8; j++)
        #pragma unroll
        for (int i = 0; i < 4; i++) acc[j][i] = 0.f;

    // prologue: stage chunk 0 into buffer 0
    {
        #pragma unroll
        for (int it = 0; it < 2; it++) {
            int r = sr + it*64;
            CPASYNC16(sb + (uint32_t)((r*XF + sc) * 4),
                      X + (size_t)(row0 + r) * DM_ + sc);
        }
        CPASYNC16(sb + (uint32_t)((10240 + wr*WS) * 4 + wg*2),
                  Wh + (size_t)(col0 + wr) * DM_ + wg);
        CPCOMMIT();
    }

    int p = 0;
    for (int c = 0; c < 16; c++) {
        CPWAIT0();
        __syncthreads();
        if (c < 15) {
            #pragma unroll
            for (int it = 0; it < 2; it++) {
                int r = sr + it*64;
                CPASYNC16(sb + (uint32_t)((((p^1)*5120) + r*XF + sc) * 4),
                          X + (size_t)(row0 + r) * DM_ + (c+1)*32 + sc);
            }
            CPASYNC16(sb + (uint32_t)((10240 + (p^1)*2560 + wr*WS) * 4 + wg*2),
                      Wh + (size_t)(col0 + wr) * DM_ + (c+1)*32 + wg);
            CPCOMMIT();
        }

        const float*    Xp = smf + p*5120;
        const uint32_t* Wp = smu + 10240 + p*2560;

        #pragma unroll
        for (int kk = 0; kk < 2; kk++) {
            uint32_t a[4];
            const float* xb = Xp + (m0 + lq)*XF + kk*16 + 2*lr;
            a[0] = ldsf2h(xb);
            a[1] = ldsf2h(xb + 8*XF);
            a[2] = ldsf2h(xb + 8);
            a[3] = ldsf2h(xb + 8*XF + 8);
            #pragma unroll
            for (int j = 0; j < 8; j++) {
                const uint32_t* wb = Wp + (n0 + j*8 + lq)*WS + kk*8 + lr;
                mma_f16(acc[j], a, wb[0], wb[4]);
            }
        }
        p ^= 1;
    }

    // epilogue: bias, cvt fp16, scatter head-major
    const int r0g = row0 + m0 + lq;
    const int r1g = r0g + 8;
    #pragma unroll
    for (int j = 0; j < 8; j++) {
        int jj = col0 + n0 + j*8 + 2*lr;
        float2 bs = *(const float2*)(bias + jj);
        int h = jj >> 6, d = jj & 63;
        {
            int b = r0g >> 11, n = r0g & 2047;
            uint32_t o = f2h2(acc[j][0] + bs.x, acc[j][1] + bs.y);
            *(uint32_t*)(outp + (((size_t)(b*H_ + h) * NQ_) + n) * HD_ + d) = o;
        }
        {
            int b = r1g >> 11, n = r1g & 2047;
            uint32_t o = f2h2(acc[j][2] + bs.x, acc[j][3] + bs.y);
            *(uint32_t*)(outp + (((size_t)(b*H_ + h) * NQ_) + n) * HD_ + d) = o;
        }
    }
}

// ---------------------------------------------------------------------------
// diag extraction
// ---------------------------------------------------------------------------
__global__ void diag_kernel(const float* __restrict__ pearson)
{
    int idx = blockIdx.x * 256 + threadIdx.x;
    if (idx < B_*H_*NK_) {
        int k  = idx & (NK_ - 1);
        int bh = idx >> 11;
        g_diag[idx] = pearson[((size_t)bh * NK_ + k) * NK_ + k];
    }
}

// ---------------------------------------------------------------------------
// Fused attention: fp16 m16n8k16, fixed-base softmax. 64 q-rows per CTA,
// 128 threads (4 warps x 16 rows). 27.9 KB smem -> finer wave granularity
// (grid 512) + more resident CTAs/SM. Per-warp code identical to R6.
// grid (NQ/64, H, B)
// ---------------------------------------------------------------------------
#define ATTN_SMEM ((3*64*SH2) * 4 + 64 * 4)

__global__ __launch_bounds__(128) void attn_kernel(
    const float* __restrict__ mask, float* __restrict__ out)
{
    extern __shared__ uint32_t smu[];
    uint32_t* Ks = smu;                    // 64 x SH2 (K[n][d] half2)
    uint32_t* Vs = Ks + 64*SH2;            // 64 x SH2 (V[k][d] half2)
    uint32_t* Ps = Vs + 64*SH2;            // 64 x SH2 (Q staging, then P)
    float*    ds = (float*)(Ps + 64*SH2);  // 64 diag

    const int tid  = threadIdx.x;
    const int lane = tid & 31, warp = tid >> 5;
    const int lq = lane >> 2, lr = lane & 3;
    const int m0 = warp * 16;
    const int q0 = blockIdx.x * 64;
    const int h  = blockIdx.y;
    const int b  = blockIdx.z;
    const int bh = b * H_ + h;

    const __half* Qg = g_Q + (size_t)bh * NQ_ * HD_ + (size_t)q0 * HD_;
    const __half* Kg = g_K + (size_t)bh * NK_ * HD_;
    const __half* Vg = g_V + (size_t)bh * NK_ * HD_;
    const float*  dg = g_diag + (size_t)bh * NK_;
    const float*  mg = mask + ((size_t)bh * NQ_ + q0) * NK_;

    // ---- stage Q into Ps (raw fp16 copy), extract persistent A-frags ----
    #pragma unroll
    for (int it = 0; it < 4; it++) {
        int e = it*128 + tid;
        int r = e >> 3, c8 = (e & 7) << 3;
        *(uint4*)&Ps[r*SH2 + (c8 >> 1)] = *(const uint4*)(Qg + (size_t)r * HD_ + c8);
    }
    __syncthreads();

    uint32_t qf[4][4];
    #pragma unroll
    for (int kk = 0; kk < 4; kk++) {
        int ab = (m0 + lq)*SH2 + kk*8 + lr;
        qf[kk][0] = Ps[ab];
        qf[kk][1] = Ps[ab + 8*SH2];
        qf[kk][2] = Ps[ab + 4];
        qf[kk][3] = Ps[ab + 8*SH2 + 4];
    }

    // ldmatrix lane base for V (rows k, cols d)
    const uint32_t vs_base = smem_u32(Vs)
                           + (uint32_t)(lane & 15) * (SH2*4)
                           + (uint32_t)(lane >> 4) * 16;

    float lsum0 = 0.f, lsum1 = 0.f;
    float oacc[8][4];
    #pragma unroll
    for (int j = 0; j < 8; j++)
        #pragma unroll
        for (int i = 0; i < 4; i++) oacc[j][i] = 0.f;

    const float* mr0 = mg + (size_t)(m0 + lq) * NK_ + 2*lr;
    const float* mr1 = mr0 + (size_t)8 * NK_;

    for (int kt = 0; kt < NK_/64; kt++) {
        __syncthreads();   // prior-tile PV reads of Ks/Vs/Ps done

        // ---- stage K and V tiles (raw fp16 uint4 copies) + diag ----
        const __half* Kt = Kg + (size_t)kt * 64 * HD_;
        const __half* Vt = Vg + (size_t)kt * 64 * HD_;
        #pragma unroll
        for (int it = 0; it < 4; it++) {
            int e = it*128 + tid;
            int r = e >> 3, c8 = (e & 7) << 3;
            *(uint4*)&Ks[r*SH2 + (c8 >> 1)] = *(const uint4*)(Kt + (size_t)r * HD_ + c8);
            *(uint4*)&Vs[r*SH2 + (c8 >> 1)] = *(const uint4*)(Vt + (size_t)r * HD_ + c8);
        }
        if (tid < 16) ((float4*)ds)[tid] = ((const float4*)(dg + kt*64))[tid];
        __syncthreads();

        // ---- S = Q @ K^T ----
        float sacc[8][4];
        #pragma unroll
        for (int j = 0; j < 8; j++)
            #pragma unroll
            for (int i = 0; i < 4; i++) sacc[j][i] = 0.f;

        #pragma unroll
        for (int kk = 0; kk < 4; kk++) {
            #pragma unroll
            for (int j = 0; j < 8; j++) {
                int bb = (j*8 + lq)*SH2 + kk*8 + lr;
                mma_f16(sacc[j], qf[kk], Ks[bb], Ks[bb + 4]);
            }
        }

        // ---- fixed-base softmax + mask*diag, store P (fp16) ----
        const float* mp0 = mr0 + kt*64;
        const float* mp1 = mr1 + kt*64;
        #pragma unroll
        for (int j = 0; j < 8; j++) {
            float2 mk0 = *(const float2*)(mp0 + j*8);
            float2 mk1 = *(const float2*)(mp1 + j*8);
            float2 d2  = *(const float2*)(ds + j*8 + 2*lr);
            float p0 = fast_ex2(sacc[j][0] * EXP2C);
            float p1 = fast_ex2(sacc[j][1] * EXP2C);
            float p2 = fast_ex2(sacc[j][2] * EXP2C);
            float p3 = fast_ex2(sacc[j][3] * EXP2C);
            lsum0 += p0 + p1;
            lsum1 += p2 + p3;
            Ps[(m0 + lq)*SH2 + j*4 + lr]     = f2h2(p0 * mk0.x * d2.x, p1 * mk0.y * d2.y);
            Ps[(m0 + lq + 8)*SH2 + j*4 + lr] = f2h2(p2 * mk1.x * d2.x, p3 * mk1.y * d2.y);
        }
        __syncwarp();   // P strip is warp-private

        // ---- O += P @ V ----
        #pragma unroll
        for (int kk = 0; kk < 4; kk++) {
            uint32_t pa[4];
            int ab = (m0 + lq)*SH2 + kk*8 + lr;
            pa[0] = Ps[ab];
            pa[1] = Ps[ab + 8*SH2];
            pa[2] = Ps[ab + 4];
            pa[3] = Ps[ab + 8*SH2 + 4];
            #pragma unroll
            for (int jp = 0; jp < 4; jp++) {
                uint32_t vb[4];
                ldsm_x4_t(vb, vs_base + (uint32_t)kk*(16*SH2*4) + (uint32_t)jp*32);
                mma_f16(oacc[2*jp],     pa, vb[0], vb[1]);
                mma_f16(oacc[2*jp + 1], pa, vb[2], vb[3]);
            }
        }
    }

    // ---- final l reduction over the quad and store ----
    lsum0 += __shfl_xor_sync(0xffffffffu, lsum0, 1);
    lsum0 += __shfl_xor_sync(0xffffffffu, lsum0, 2);
    lsum1 += __shfl_xor_sync(0xffffffffu, lsum1, 1);
    lsum1 += __shfl_xor_sync(0xffffffffu, lsum1, 2);
    float inv0 = 1.f / lsum0;
    float inv1 = 1.f / lsum1;

    const int r0 = q0 + m0 + lq;
    const int r1 = r0 + 8;
    #pragma unroll
    for (int j = 0; j < 8; j++) {
        int c = h*HD_ + j*8 + 2*lr;
        float2 o0; o0.x = oacc[j][0]*inv0; o0.y = oacc[j][1]*inv0;
        float2 o1; o1.x = oacc[j][2]*inv1; o1.y = oacc[j][3]*inv1;
        *(float2*)(out + ((size_t)b*NQ_ + r0)*DM_ + c) = o0;
        *(float2*)(out + ((size_t)b*NQ_ + r1)*DM_ + c) = o1;
    }
}

// ---------------------------------------------------------------------------
extern "C" void kernel_launch(void* const* d_in, const int* in_sizes, int n_in,
                              void* d_out, int out_size)
{
    const float* q       = (const float*)d_in[0];
    const float* k       = (const float*)d_in[1];
    const float* v       = (const float*)d_in[2];
    const float* mask    = (const float*)d_in[3];
    const float* pearson = (const float*)d_in[4];
    const float* Wq      = (const float*)d_in[5];
    const float* bq      = (const float*)d_in[6];
    const float* Wk      = (const float*)d_in[7];
    const float* bk      = (const float*)d_in[8];
    const float* Wv      = (const float*)d_in[9];
    const float* bv      = (const float*)d_in[10];
    float* out = (float*)d_out;

    cudaFuncSetAttribute(proj_kernel,
                         cudaFuncAttributeMaxDynamicSharedMemorySize, PROJ_SMEM);
    cudaFuncSetAttribute(attn_kernel,
                         cudaFuncAttributeMaxDynamicSharedMemorySize, ATTN_SMEM);

    wcvt_kernel<<<768, 256>>>(Wq, Wk, Wv);
    diag_kernel<<<(B_*H_*NK_ + 255)/256, 256>>>(pearson);

    dim3 pg(DM_/128, (B_*NQ_)/128, 3);
    proj_kernel<<<pg, 512, PROJ_SMEM>>>(q, k, v, bq, bk, bv);

    dim3 ag(NQ_/64, H_, B_);
    attn_kernel<<<ag, 128, ATTN_SMEM>>>(mask, out);
}

// round 12
// speedup vs baseline: 1.5317x; 1.5317x over previous
#include <cuda_runtime.h>
#include <cuda_fp16.h>
#include <math.h>
#include <stdint.h>

#define B_   2
#define H_   8
#define NQ_  2048
#define NK_  2048
#define DM_  512
#define HD_  64
#define EXP2C 0.18033688011112042f   /* 0.125 * log2(e) */

#define SH2 36   // half2 words per 64-half row; 36%32==4 -> conflict-free frags
#define XF  40   // f32 words per 32-f32 row (32+8 pad); conflict-free float2 frags
#define WS  20   // uint32 words per 32-half W row (16+4 pad); 20*lq+lr banks distinct

// Scratch (allocation-free rule: __device__ globals)
__device__ __half g_Q[B_*H_*NQ_*HD_];
__device__ __half g_K[B_*H_*NK_*HD_];
__device__ __half g_V[B_*H_*NK_*HD_];
__device__ __half g_Wh[3*DM_*DM_];
__device__ float  g_diag[B_*H_*NK_];

// ---------------------------------------------------------------------------
// helpers
// ---------------------------------------------------------------------------
__device__ __forceinline__ float fast_ex2(float x) {
    float y;
    asm("ex2.approx.ftz.f32 %0, %1;" : "=f"(y) : "f"(x));
    return y;
}
__device__ __forceinline__ uint32_t f2h2(float lo, float hi) {
    __half2 h = __floats2half2_rn(lo, hi);
    return *reinterpret_cast<uint32_t*>(&h);
}
__device__ __forceinline__ uint32_t ldsf2h(const float* p) {
    float2 v = *(const float2*)p;
    return f2h2(v.x, v.y);
}
__device__ __forceinline__ void mma_f16(float c[4], const uint32_t a[4],
                                        uint32_t b0, uint32_t b1) {
    asm volatile(
        "mma.sync.aligned.m16n8k16.row.col.f32.f16.f16.f32 "
        "{%0,%1,%2,%3}, {%4,%5,%6,%7}, {%8,%9}, {%0,%1,%2,%3};\n"
        : "+f"(c[0]), "+f"(c[1]), "+f"(c[2]), "+f"(c[3])
        : "r"(a[0]), "r"(a[1]), "r"(a[2]), "r"(a[3]), "r"(b0), "r"(b1));
}
__device__ __forceinline__ void ldsm_x4_t(uint32_t r[4], uint32_t addr) {
    asm volatile(
        "ldmatrix.sync.aligned.m8n8.x4.trans.shared.b16 {%0,%1,%2,%3}, [%4];"
        : "=r"(r[0]), "=r"(r[1]), "=r"(r[2]), "=r"(r[3]) : "r"(addr));
}
__device__ __forceinline__ uint32_t smem_u32(const void* p) {
    uint32_t a;
    asm("{ .reg .u64 t; cvta.to.shared.u64 t, %1; cvt.u32.u64 %0, t; }"
        : "=r"(a) : "l"(p));
    return a;
}
#define CPASYNC16(dst, src) \
    asm volatile("cp.async.cg.shared.global [%0], [%1], 16;" :: "r"(dst), "l"(src))
#define CPCOMMIT() asm volatile("cp.async.commit_group;" ::: "memory")
#define CPWAIT0()  asm volatile("cp.async.wait_group 0;"  ::: "memory")

// ---------------------------------------------------------------------------
// W fp32 -> fp16 pre-convert: g_Wh[z][n][k], k contiguous.
// ---------------------------------------------------------------------------
__global__ void wcvt_kernel(const float* __restrict__ Wq,
                            const float* __restrict__ Wk,
                            const float* __restrict__ Wv)
{
    int idx = blockIdx.x * 256 + threadIdx.x;        // 0 .. 196607 (float4)
    const float* src = (idx < 65536) ? Wq : (idx < 131072 ? Wk : Wv);
    float4 w = *(const float4*)(src + (size_t)(idx & 65535) * 4);
    uint2 o;
    o.x = f2h2(w.x, w.y);
    o.y = f2h2(w.z, w.w);
    *(uint2*)(g_Wh + (size_t)idx * 4) = o;
}

// ---------------------------------------------------------------------------
// Projection, fp16 m16n8k16, cp.async double-buffered, 512 threads.
// Tile: M=128 x N=128, K-chunk 32 (16 chunks).
// X staged f32 (stride XF); W staged fp16 (stride WS words) -> B-frags are
// raw LDS.32, no CVT in the hot loop.
// smem (f32 words): X[2]@0/5120, W[2]@10240/12800  -> 61440 B.
// grid (DM/128, B*N/128, 3); block 512 (16 warps: m=warp&7, n=warp>>3).
// ---------------------------------------------------------------------------
#define PROJ_SMEM (15360 * 4)

__global__ __launch_bounds__(512) void proj_kernel(
    const float* __restrict__ q, const float* __restrict__ k,
    const float* __restrict__ v,
    const float* __restrict__ bq, const float* __restrict__ bk,
    const float* __restrict__ bv)
{
    extern __shared__ float smf[];
    uint32_t* smu = (uint32_t*)smf;
    const uint32_t sb = smem_u32(smf);

    const float *X, *bias;
    const __half* Wh;
    __half* outp;
    if (blockIdx.z == 0)      { X = q; bias = bq; Wh = g_Wh;              outp = g_Q; }
    else if (blockIdx.z == 1) { X = k; bias = bk; Wh = g_Wh + DM_*DM_;    outp = g_K; }
    else                      { X = v; bias = bv; Wh = g_Wh + 2*DM_*DM_;  outp = g_V; }

    const int tid  = threadIdx.x;
    const int lane = tid & 31, warp = tid >> 5;
    const int lq = lane >> 2, lr = lane & 3;
    const int m0 = (warp & 7) * 16;
    const int n0 = (warp >> 3) * 64;
    const int row0 = blockIdx.y * 128;
    const int col0 = blockIdx.x * 128;

    // X staging: 512 thr x 16B x 2 it = 16 KB (128 rows x 32 f32)
    const int sr = tid >> 3;           // 0..63, r = sr + it*64
    const int sc = (tid & 7) << 2;     // f32 col 0,4,..28
    // W staging: 512 thr x 16B = 8 KB (128 rows x 32 halfs)
    const int wr = tid >> 2;           // 0..127
    const int wg = (tid & 3) << 3;     // half col 0,8,16,24

    float acc[8][4];
    #pragma unroll
    for (int j = 0; j < 8; j++)
        #pragma unroll
        for (int i = 0; i < 4; i++) acc[j][i] = 0.f;

    // prologue: stage chunk 0 into buffer 0
    {
        #pragma unroll
        for (int it = 0; it < 2; it++) {
            int r = sr + it*64;
            CPASYNC16(sb + (uint32_t)((r*XF + sc) * 4),
                      X + (size_t)(row0 + r) * DM_ + sc);
        }
        CPASYNC16(sb + (uint32_t)((10240 + wr*WS) * 4 + wg*2),
                  Wh + (size_t)(col0 + wr) * DM_ + wg);
        CPCOMMIT();
    }

    int p = 0;
    for (int c = 0; c < 16; c++) {
        CPWAIT0();
        __syncthreads();
        if (c < 15) {
            #pragma unroll
            for (int it = 0; it < 2; it++) {
                int r = sr + it*64;
                CPASYNC16(sb + (uint32_t)((((p^1)*5120) + r*XF + sc) * 4),
                          X + (size_t)(row0 + r) * DM_ + (c+1)*32 + sc);
            }
            CPASYNC16(sb + (uint32_t)((10240 + (p^1)*2560 + wr*WS) * 4 + wg*2),
                      Wh + (size_t)(col0 + wr) * DM_ + (c+1)*32 + wg);
            CPCOMMIT();
        }

        const float*    Xp = smf + p*5120;
        const uint32_t* Wp = smu + 10240 + p*2560;

        #pragma unroll
        for (int kk = 0; kk < 2; kk++) {
            uint32_t a[4];
            const float* xb = Xp + (m0 + lq)*XF + kk*16 + 2*lr;
            a[0] = ldsf2h(xb);
            a[1] = ldsf2h(xb + 8*XF);
            a[2] = ldsf2h(xb + 8);
            a[3] = ldsf2h(xb + 8*XF + 8);
            #pragma unroll
            for (int j = 0; j < 8; j++) {
                const uint32_t* wb = Wp + (n0 + j*8 + lq)*WS + kk*8 + lr;
                mma_f16(acc[j], a, wb[0], wb[4]);
            }
        }
        p ^= 1;
    }

    // epilogue: bias, cvt fp16, scatter head-major
    const int r0g = row0 + m0 + lq;
    const int r1g = r0g + 8;
    #pragma unroll
    for (int j = 0; j < 8; j++) {
        int jj = col0 + n0 + j*8 + 2*lr;
        float2 bs = *(const float2*)(bias + jj);
        int h = jj >> 6, d = jj & 63;
        {
            int b = r0g >> 11, n = r0g & 2047;
            uint32_t o = f2h2(acc[j][0] + bs.x, acc[j][1] + bs.y);
            *(uint32_t*)(outp + (((size_t)(b*H_ + h) * NQ_) + n) * HD_ + d) = o;
        }
        {
            int b = r1g >> 11, n = r1g & 2047;
            uint32_t o = f2h2(acc[j][2] + bs.x, acc[j][3] + bs.y);
            *(uint32_t*)(outp + (((size_t)(b*H_ + h) * NQ_) + n) * HD_ + d) = o;
        }
    }
}

// ---------------------------------------------------------------------------
// diag extraction
// ---------------------------------------------------------------------------
__global__ void diag_kernel(const float* __restrict__ pearson)
{
    int idx = blockIdx.x * 256 + threadIdx.x;
    if (idx < B_*H_*NK_) {
        int k  = idx & (NK_ - 1);
        int bh = idx >> 11;
        g_diag[idx] = pearson[((size_t)bh * NK_ + k) * NK_ + k];
    }
}

// ---------------------------------------------------------------------------
// Fused attention (R6 shape, proven ~120us): fp16 m16n8k16, fixed-base
// softmax. 256 threads (8 warps), 128 q-rows per CTA; 64-key tiles.
// 37 KB smem -> 6 CTAs/SM; occupancy is the latency-hiding mechanism.
// grid (NQ/128, H, B)
// ---------------------------------------------------------------------------
#define ATTN_SMEM ((64*SH2 + 64*SH2 + 128*SH2) * 4 + 64 * 4)

__global__ __launch_bounds__(256) void attn_kernel(
    const float* __restrict__ mask, float* __restrict__ out)
{
    extern __shared__ uint32_t smu[];
    uint32_t* Ks = smu;                    // 64  x SH2 (K[n][d] half2)
    uint32_t* Vs = Ks + 64*SH2;            // 64  x SH2 (V[k][d] half2)
    uint32_t* Ps = Vs + 64*SH2;            // 128 x SH2 (Q staging, then P)
    float*    ds = (float*)(Ps + 128*SH2); // 64 diag

    const int tid  = threadIdx.x;
    const int lane = tid & 31, warp = tid >> 5;
    const int lq = lane >> 2, lr = lane & 3;
    const int m0 = warp * 16;
    const int q0 = blockIdx.x * 128;
    const int h  = blockIdx.y;
    const int b  = blockIdx.z;
    const int bh = b * H_ + h;

    const __half* Qg = g_Q + (size_t)bh * NQ_ * HD_ + (size_t)q0 * HD_;
    const __half* Kg = g_K + (size_t)bh * NK_ * HD_;
    const __half* Vg = g_V + (size_t)bh * NK_ * HD_;
    const float*  dg = g_diag + (size_t)bh * NK_;
    const float*  mg = mask + ((size_t)bh * NQ_ + q0) * NK_;

    // ---- stage Q into Ps (raw fp16 copy), extract persistent A-frags ----
    #pragma unroll
    for (int it = 0; it < 4; it++) {
        int e = it*256 + tid;
        int r = e >> 3, c8 = (e & 7) << 3;
        *(uint4*)&Ps[r*SH2 + (c8 >> 1)] = *(const uint4*)(Qg + (size_t)r * HD_ + c8);
    }
    __syncthreads();

    uint32_t qf[4][4];
    #pragma unroll
    for (int kk = 0; kk < 4; kk++) {
        int ab = (m0 + lq)*SH2 + kk*8 + lr;
        qf[kk][0] = Ps[ab];
        qf[kk][1] = Ps[ab + 8*SH2];
        qf[kk][2] = Ps[ab + 4];
        qf[kk][3] = Ps[ab + 8*SH2 + 4];
    }

    // ldmatrix lane base for V (rows k, cols d)
    const uint32_t vs_base = smem_u32(Vs)
                           + (uint32_t)(lane & 15) * (SH2*4)
                           + (uint32_t)(lane >> 4) * 16;

    float lsum0 = 0.f, lsum1 = 0.f;
    float oacc[8][4];
    #pragma unroll
    for (int j = 0; j < 8; j++)
        #pragma unroll
        for (int i = 0; i < 4; i++) oacc[j][i] = 0.f;

    const float* mr0 = mg + (size_t)(m0 + lq) * NK_ + 2*lr;
    const float* mr1 = mr0 + (size_t)8 * NK_;

    for (int kt = 0; kt < NK_/64; kt++) {
        __syncthreads();   // prior-tile PV reads of Ks/Vs/Ps done

        // ---- stage K and V tiles (raw fp16 uint4 copies) + diag ----
        const __half* Kt = Kg + (size_t)kt * 64 * HD_;
        const __half* Vt = Vg + (size_t)kt * 64 * HD_;
        #pragma unroll
        for (int it = 0; it < 2; it++) {
            int e = it*256 + tid;
            int r = e >> 3, c8 = (e & 7) << 3;
            *(uint4*)&Ks[r*SH2 + (c8 >> 1)] = *(const uint4*)(Kt + (size_t)r * HD_ + c8);
            *(uint4*)&Vs[r*SH2 + (c8 >> 1)] = *(const uint4*)(Vt + (size_t)r * HD_ + c8);
        }
        if (tid < 16) ((float4*)ds)[tid] = ((const float4*)(dg + kt*64))[tid];
        __syncthreads();

        // ---- S = Q @ K^T ----
        float sacc[8][4];
        #pragma unroll
        for (int j = 0; j < 8; j++)
            #pragma unroll
            for (int i = 0; i < 4; i++) sacc[j][i] = 0.f;

        #pragma unroll
        for (int kk = 0; kk < 4; kk++) {
            #pragma unroll
            for (int j = 0; j < 8; j++) {
                int bb = (j*8 + lq)*SH2 + kk*8 + lr;
                mma_f16(sacc[j], qf[kk], Ks[bb], Ks[bb + 4]);
            }
        }

        // ---- fixed-base softmax + mask*diag, store P (fp16) ----
        const float* mp0 = mr0 + kt*64;
        const float* mp1 = mr1 + kt*64;
        #pragma unroll
        for (int j = 0; j < 8; j++) {
            float2 mk0 = *(const float2*)(mp0 + j*8);
            float2 mk1 = *(const float2*)(mp1 + j*8);
            float2 d2  = *(const float2*)(ds + j*8 + 2*lr);
            float p0 = fast_ex2(sacc[j][0] * EXP2C);
            float p1 = fast_ex2(sacc[j][1] * EXP2C);
            float p2 = fast_ex2(sacc[j][2] * EXP2C);
            float p3 = fast_ex2(sacc[j][3] * EXP2C);
            lsum0 += p0 + p1;
            lsum1 += p2 + p3;
            Ps[(m0 + lq)*SH2 + j*4 + lr]     = f2h2(p0 * mk0.x * d2.x, p1 * mk0.y * d2.y);
            Ps[(m0 + lq + 8)*SH2 + j*4 + lr] = f2h2(p2 * mk1.x * d2.x, p3 * mk1.y * d2.y);
        }
        __syncwarp();   // P strip is warp-private

        // ---- O += P @ V ----
        #pragma unroll
        for (int kk = 0; kk < 4; kk++) {
            uint32_t pa[4];
            int ab = (m0 + lq)*SH2 + kk*8 + lr;
            pa[0] = Ps[ab];
            pa[1] = Ps[ab + 8*SH2];
            pa[2] = Ps[ab + 4];
            pa[3] = Ps[ab + 8*SH2 + 4];
            #pragma unroll
            for (int jp = 0; jp < 4; jp++) {
                uint32_t vb[4];
                ldsm_x4_t(vb, vs_base + (uint32_t)kk*(16*SH2*4) + (uint32_t)jp*32);
                mma_f16(oacc[2*jp],     pa, vb[0], vb[1]);
                mma_f16(oacc[2*jp + 1], pa, vb[2], vb[3]);
            }
        }
    }

    // ---- final l reduction over the quad and store ----
    lsum0 += __shfl_xor_sync(0xffffffffu, lsum0, 1);
    lsum0 += __shfl_xor_sync(0xffffffffu, lsum0, 2);
    lsum1 += __shfl_xor_sync(0xffffffffu, lsum1, 1);
    lsum1 += __shfl_xor_sync(0xffffffffu, lsum1, 2);
    float inv0 = 1.f / lsum0;
    float inv1 = 1.f / lsum1;

    const int r0 = q0 + m0 + lq;
    const int r1 = r0 + 8;
    #pragma unroll
    for (int j = 0; j < 8; j++) {
        int c = h*HD_ + j*8 + 2*lr;
        float2 o0; o0.x = oacc[j][0]*inv0; o0.y = oacc[j][1]*inv0;
        float2 o1; o1.x = oacc[j][2]*inv1; o1.y = oacc[j][3]*inv1;
        *(float2*)(out + ((size_t)b*NQ_ + r0)*DM_ + c) = o0;
        *(float2*)(out + ((size_t)b*NQ_ + r1)*DM_ + c) = o1;
    }
}

// ---------------------------------------------------------------------------
extern "C" void kernel_launch(void* const* d_in, const int* in_sizes, int n_in,
                              void* d_out, int out_size)
{
    const float* q       = (const float*)d_in[0];
    const float* k       = (const float*)d_in[1];
    const float* v       = (const float*)d_in[2];
    const float* mask    = (const float*)d_in[3];
    const float* pearson = (const float*)d_in[4];
    const float* Wq      = (const float*)d_in[5];
    const float* bq      = (const float*)d_in[6];
    const float* Wk      = (const float*)d_in[7];
    const float* bk      = (const float*)d_in[8];
    const float* Wv      = (const float*)d_in[9];
    const float* bv      = (const float*)d_in[10];
    float* out = (float*)d_out;

    cudaFuncSetAttribute(proj_kernel,
                         cudaFuncAttributeMaxDynamicSharedMemorySize, PROJ_SMEM);
    cudaFuncSetAttribute(attn_kernel,
                         cudaFuncAttributeMaxDynamicSharedMemorySize, ATTN_SMEM);

    wcvt_kernel<<<768, 256>>>(Wq, Wk, Wv);
    diag_kernel<<<(B_*H_*NK_ + 255)/256, 256>>>(pearson);

    dim3 pg(DM_/128, (B_*NQ_)/128, 3);
    proj_kernel<<<pg, 512, PROJ_SMEM>>>(q, k, v, bq, bk, bv);

    dim3 ag(NQ_/128, H_, B_);
    attn_kernel<<<ag, 256, ATTN_SMEM>>>(mask, out);
}

// round 13
// speedup vs baseline: 1.7000x; 1.1099x over previous
#include <cuda_runtime.h>
#include <cuda_fp16.h>
#include <math.h>
#include <stdint.h>

#define B_   2
#define H_   8
#define NQ_  2048
#define NK_  2048
#define DM_  512
#define HD_  64
#define EXP2C 0.18033688011112042f   /* 0.125 * log2(e) */

#define SH2 36   // half2 words per 64-half row; 36%32==4 -> conflict-free frags
#define XF  40   // f32 words per 32-f32 row; conflict-free float2 frags
#define WS  20   // uint32 words per 32-half W row
#define MS  68   // f32 words per 64-f32 mask row; 68%32==4 -> <=2-way on float2

// Scratch (allocation-free rule: __device__ globals)
__device__ __half g_Q[B_*H_*NQ_*HD_];
__device__ __half g_K[B_*H_*NK_*HD_];
__device__ __half g_V[B_*H_*NK_*HD_];
__device__ __half g_Wh[3*DM_*DM_];
__device__ float  g_diag[B_*H_*NK_];

// ---------------------------------------------------------------------------
// helpers
// ---------------------------------------------------------------------------
__device__ __forceinline__ float fast_ex2(float x) {
    float y;
    asm("ex2.approx.ftz.f32 %0, %1;" : "=f"(y) : "f"(x));
    return y;
}
__device__ __forceinline__ uint32_t f2h2(float lo, float hi) {
    __half2 h = __floats2half2_rn(lo, hi);
    return *reinterpret_cast<uint32_t*>(&h);
}
__device__ __forceinline__ uint32_t ldsf2h(const float* p) {
    float2 v = *(const float2*)p;
    return f2h2(v.x, v.y);
}
__device__ __forceinline__ void mma_f16(float c[4], const uint32_t a[4],
                                        uint32_t b0, uint32_t b1) {
    asm volatile(
        "mma.sync.aligned.m16n8k16.row.col.f32.f16.f16.f32 "
        "{%0,%1,%2,%3}, {%4,%5,%6,%7}, {%8,%9}, {%0,%1,%2,%3};\n"
        : "+f"(c[0]), "+f"(c[1]), "+f"(c[2]), "+f"(c[3])
        : "r"(a[0]), "r"(a[1]), "r"(a[2]), "r"(a[3]), "r"(b0), "r"(b1));
}
__device__ __forceinline__ void ldsm_x4_t(uint32_t r[4], uint32_t addr) {
    asm volatile(
        "ldmatrix.sync.aligned.m8n8.x4.trans.shared.b16 {%0,%1,%2,%3}, [%4];"
        : "=r"(r[0]), "=r"(r[1]), "=r"(r[2]), "=r"(r[3]) : "r"(addr));
}
__device__ __forceinline__ uint32_t smem_u32(const void* p) {
    uint32_t a;
    asm("{ .reg .u64 t; cvta.to.shared.u64 t, %1; cvt.u32.u64 %0, t; }"
        : "=r"(a) : "l"(p));
    return a;
}
#define CPASYNC16(dst, src) \
    asm volatile("cp.async.cg.shared.global [%0], [%1], 16;" :: "r"(dst), "l"(src))
#define CPCOMMIT()  asm volatile("cp.async.commit_group;" ::: "memory")
#define CPWAIT0()   asm volatile("cp.async.wait_group 0;"  ::: "memory")
#define CPWAIT1()   asm volatile("cp.async.wait_group 1;"  ::: "memory")

// ---------------------------------------------------------------------------
// W fp32 -> fp16 pre-convert
// ---------------------------------------------------------------------------
__global__ void wcvt_kernel(const float* __restrict__ Wq,
                            const float* __restrict__ Wk,
                            const float* __restrict__ Wv)
{
    int idx = blockIdx.x * 256 + threadIdx.x;        // 0 .. 196607 (float4)
    const float* src = (idx < 65536) ? Wq : (idx < 131072 ? Wk : Wv);
    float4 w = *(const float4*)(src + (size_t)(idx & 65535) * 4);
    uint2 o;
    o.x = f2h2(w.x, w.y);
    o.y = f2h2(w.z, w.w);
    *(uint2*)(g_Wh + (size_t)idx * 4) = o;
}

// ---------------------------------------------------------------------------
// Projection (R12 proven): fp16 m16n8k16, cp.async double-buffered, 512 thr.
// ---------------------------------------------------------------------------
#define PROJ_SMEM (15360 * 4)

__global__ __launch_bounds__(512) void proj_kernel(
    const float* __restrict__ q, const float* __restrict__ k,
    const float* __restrict__ v,
    const float* __restrict__ bq, const float* __restrict__ bk,
    const float* __restrict__ bv)
{
    extern __shared__ float smf[];
    uint32_t* smu = (uint32_t*)smf;
    const uint32_t sb = smem_u32(smf);

    const float *X, *bias;
    const __half* Wh;
    __half* outp;
    if (blockIdx.z == 0)      { X = q; bias = bq; Wh = g_Wh;              outp = g_Q; }
    else if (blockIdx.z == 1) { X = k; bias = bk; Wh = g_Wh + DM_*DM_;    outp = g_K; }
    else                      { X = v; bias = bv; Wh = g_Wh + 2*DM_*DM_;  outp = g_V; }

    const int tid  = threadIdx.x;
    const int lane = tid & 31, warp = tid >> 5;
    const int lq = lane >> 2, lr = lane & 3;
    const int m0 = (warp & 7) * 16;
    const int n0 = (warp >> 3) * 64;
    const int row0 = blockIdx.y * 128;
    const int col0 = blockIdx.x * 128;

    const int sr = tid >> 3;
    const int sc = (tid & 7) << 2;
    const int wr = tid >> 2;
    const int wg = (tid & 3) << 3;

    float acc[8][4];
    #pragma unroll
    for (int j = 0; j < 8; j++)
        #pragma unroll
        for (int i = 0; i < 4; i++) acc[j][i] = 0.f;

    {
        #pragma unroll
        for (int it = 0; it < 2; it++) {
            int r = sr + it*64;
            CPASYNC16(sb + (uint32_t)((r*XF + sc) * 4),
                      X + (size_t)(row0 + r) * DM_ + sc);
        }
        CPASYNC16(sb + (uint32_t)((10240 + wr*WS) * 4 + wg*2),
                  Wh + (size_t)(col0 + wr) * DM_ + wg);
        CPCOMMIT();
    }

    int p = 0;
    for (int c = 0; c < 16; c++) {
        CPWAIT0();
        __syncthreads();
        if (c < 15) {
            #pragma unroll
            for (int it = 0; it < 2; it++) {
                int r = sr + it*64;
                CPASYNC16(sb + (uint32_t)((((p^1)*5120) + r*XF + sc) * 4),
                          X + (size_t)(row0 + r) * DM_ + (c+1)*32 + sc);
            }
            CPASYNC16(sb + (uint32_t)((10240 + (p^1)*2560 + wr*WS) * 4 + wg*2),
                      Wh + (size_t)(col0 + wr) * DM_ + (c+1)*32 + wg);
            CPCOMMIT();
        }

        const float*    Xp = smf + p*5120;
        const uint32_t* Wp = smu + 10240 + p*2560;

        #pragma unroll
        for (int kk = 0; kk < 2; kk++) {
            uint32_t a[4];
            const float* xb = Xp + (m0 + lq)*XF + kk*16 + 2*lr;
            a[0] = ldsf2h(xb);
            a[1] = ldsf2h(xb + 8*XF);
            a[2] = ldsf2h(xb + 8);
            a[3] = ldsf2h(xb + 8*XF + 8);
            #pragma unroll
            for (int j = 0; j < 8; j++) {
                const uint32_t* wb = Wp + (n0 + j*8 + lq)*WS + kk*8 + lr;
                mma_f16(acc[j], a, wb[0], wb[4]);
            }
        }
        p ^= 1;
    }

    const int r0g = row0 + m0 + lq;
    const int r1g = r0g + 8;
    #pragma unroll
    for (int j = 0; j < 8; j++) {
        int jj = col0 + n0 + j*8 + 2*lr;
        float2 bs = *(const float2*)(bias + jj);
        int h = jj >> 6, d = jj & 63;
        {
            int b = r0g >> 11, n = r0g & 2047;
            uint32_t o = f2h2(acc[j][0] + bs.x, acc[j][1] + bs.y);
            *(uint32_t*)(outp + (((size_t)(b*H_ + h) * NQ_) + n) * HD_ + d) = o;
        }
        {
            int b = r1g >> 11, n = r1g & 2047;
            uint32_t o = f2h2(acc[j][2] + bs.x, acc[j][3] + bs.y);
            *(uint32_t*)(outp + (((size_t)(b*H_ + h) * NQ_) + n) * HD_ + d) = o;
        }
    }
}

// ---------------------------------------------------------------------------
// diag extraction
// ---------------------------------------------------------------------------
__global__ void diag_kernel(const float* __restrict__ pearson)
{
    int idx = blockIdx.x * 256 + threadIdx.x;
    if (idx < B_*H_*NK_) {
        int k  = idx & (NK_ - 1);
        int bh = idx >> 11;
        g_diag[idx] = pearson[((size_t)bh * NK_ + k) * NK_ + k];
    }
}

// ---------------------------------------------------------------------------
// Fused attention with cp.async MASK prefetch (the measured bottleneck).
// 256 threads (8 warps), 128 q-rows per CTA; 64-key tiles.
// smem words: Ks@0(2304) Vs@2304 Ps@4608(4608) ds@9216(64)
//             mask[2]@9280/17984 (8704 each, MS=68 stride) -> 106752 B.
// Regs cap residency at 2 CTAs/SM, so the +70KB smem costs no occupancy.
// grid (NQ/128, H, B)
// ---------------------------------------------------------------------------
#define MB0 9280
#define MB1 17984
#define ATTN_SMEM (26688 * 4)

__global__ __launch_bounds__(256) void attn_kernel(
    const float* __restrict__ mask, float* __restrict__ out)
{
    extern __shared__ uint32_t smu[];
    const uint32_t sb = smem_u32(smu);
    uint32_t* Ks = smu;
    uint32_t* Vs = Ks + 64*SH2;
    uint32_t* Ps = Vs + 64*SH2;
    float*    ds = (float*)(Ps + 128*SH2);

    const int tid  = threadIdx.x;
    const int lane = tid & 31, warp = tid >> 5;
    const int lq = lane >> 2, lr = lane & 3;
    const int m0 = warp * 16;
    const int q0 = blockIdx.x * 128;
    const int h  = blockIdx.y;
    const int b  = blockIdx.z;
    const int bh = b * H_ + h;

    const __half* Qg = g_Q + (size_t)bh * NQ_ * HD_ + (size_t)q0 * HD_;
    const __half* Kg = g_K + (size_t)bh * NK_ * HD_;
    const __half* Vg = g_V + (size_t)bh * NK_ * HD_;
    const float*  dg = g_diag + (size_t)bh * NK_;
    const float*  mg = mask + ((size_t)bh * NQ_ + q0) * NK_;

    // mask staging coords: 8 passes x 256 thr x 16B = 32 KB (128 rows x 64 f32)
    const int msr = tid >> 4;          // 0..15, row = msr + it*16
    const int msc = (tid & 15) << 2;   // f32 col 0,4,..60

    // ---- stage Q into Ps, extract persistent A-frags ----
    #pragma unroll
    for (int it = 0; it < 4; it++) {
        int e = it*256 + tid;
        int r = e >> 3, c8 = (e & 7) << 3;
        *(uint4*)&Ps[r*SH2 + (c8 >> 1)] = *(const uint4*)(Qg + (size_t)r * HD_ + c8);
    }
    __syncthreads();

    uint32_t qf[4][4];
    #pragma unroll
    for (int kk = 0; kk < 4; kk++) {
        int ab = (m0 + lq)*SH2 + kk*8 + lr;
        qf[kk][0] = Ps[ab];
        qf[kk][1] = Ps[ab + 8*SH2];
        qf[kk][2] = Ps[ab + 4];
        qf[kk][3] = Ps[ab + 8*SH2 + 4];
    }

    const uint32_t vs_base = smem_u32(Vs)
                           + (uint32_t)(lane & 15) * (SH2*4)
                           + (uint32_t)(lane >> 4) * 16;

    float lsum0 = 0.f, lsum1 = 0.f;
    float oacc[8][4];
    #pragma unroll
    for (int j = 0; j < 8; j++)
        #pragma unroll
        for (int i = 0; i < 4; i++) oacc[j][i] = 0.f;

    // prologue: prefetch mask tile 0 into buffer 0
    #pragma unroll
    for (int it = 0; it < 8; it++) {
        int r = msr + it*16;
        CPASYNC16(sb + (uint32_t)((MB0 + r*MS + msc) * 4),
                  mg + (size_t)r * NK_ + msc);
    }
    CPCOMMIT();

    for (int kt = 0; kt < NK_/64; kt++) {
        const int p = kt & 1;
        __syncthreads();   // prior-tile reads of Ks/Vs/Ps and mask buf done

        // ---- stage K and V tiles (plain copies; L2-resident) + diag ----
        const __half* Kt = Kg + (size_t)kt * 64 * HD_;
        const __half* Vt = Vg + (size_t)kt * 64 * HD_;
        #pragma unroll
        for (int it = 0; it < 2; it++) {
            int e = it*256 + tid;
            int r = e >> 3, c8 = (e & 7) << 3;
            *(uint4*)&Ks[r*SH2 + (c8 >> 1)] = *(const uint4*)(Kt + (size_t)r * HD_ + c8);
            *(uint4*)&Vs[r*SH2 + (c8 >> 1)] = *(const uint4*)(Vt + (size_t)r * HD_ + c8);
        }
        if (tid < 16) ((float4*)ds)[tid] = ((const float4*)(dg + kt*64))[tid];

        // ---- prefetch NEXT mask tile, then wait for CURRENT one ----
        if (kt < NK_/64 - 1) {
            const float* mn = mg + (size_t)(kt+1) * 64;
            uint32_t mb = (p ? MB0 : MB1);
            #pragma unroll
            for (int it = 0; it < 8; it++) {
                int r = msr + it*16;
                CPASYNC16(sb + (uint32_t)((mb + r*MS + msc) * 4),
                          mn + (size_t)r * NK_ + msc);
            }
            CPCOMMIT();
            CPWAIT1();      // current tile's group done; next stays in flight
        } else {
            CPWAIT0();
        }
        __syncthreads();

        const float* msk = (const float*)(smu + (p ? MB1 : MB0));

        // ---- S = Q @ K^T ----
        float sacc[8][4];
        #pragma unroll
        for (int j = 0; j < 8; j++)
            #pragma unroll
            for (int i = 0; i < 4; i++) sacc[j][i] = 0.f;

        #pragma unroll
        for (int kk = 0; kk < 4; kk++) {
            #pragma unroll
            for (int j = 0; j < 8; j++) {
                int bb = (j*8 + lq)*SH2 + kk*8 + lr;
                mma_f16(sacc[j], qf[kk], Ks[bb], Ks[bb + 4]);
            }
        }

        // ---- fixed-base softmax + mask(smem)*diag, store P (fp16) ----
        const float* mp0 = msk + (m0 + lq)*MS + 2*lr;
        const float* mp1 = mp0 + 8*MS;
        #pragma unroll
        for (int j = 0; j < 8; j++) {
            float2 mk0 = *(const float2*)(mp0 + j*8);
            float2 mk1 = *(const float2*)(mp1 + j*8);
            float2 d2  = *(const float2*)(ds + j*8 + 2*lr);
            float p0 = fast_ex2(sacc[j][0] * EXP2C);
            float p1 = fast_ex2(sacc[j][1] * EXP2C);
            float p2 = fast_ex2(sacc[j][2] * EXP2C);
            float p3 = fast_ex2(sacc[j][3] * EXP2C);
            lsum0 += p0 + p1;
            lsum1 += p2 + p3;
            Ps[(m0 + lq)*SH2 + j*4 + lr]     = f2h2(p0 * mk0.x * d2.x, p1 * mk0.y * d2.y);
            Ps[(m0 + lq + 8)*SH2 + j*4 + lr] = f2h2(p2 * mk1.x * d2.x, p3 * mk1.y * d2.y);
        }
        __syncwarp();   // P strip is warp-private

        // ---- O += P @ V ----
        #pragma unroll
        for (int kk = 0; kk < 4; kk++) {
            uint32_t pa[4];
            int ab = (m0 + lq)*SH2 + kk*8 + lr;
            pa[0] = Ps[ab];
            pa[1] = Ps[ab + 8*SH2];
            pa[2] = Ps[ab + 4];
            pa[3] = Ps[ab + 8*SH2 + 4];
            #pragma unroll
            for (int jp = 0; jp < 4; jp++) {
                uint32_t vb[4];
                ldsm_x4_t(vb, vs_base + (uint32_t)kk*(16*SH2*4) + (uint32_t)jp*32);
                mma_f16(oacc[2*jp],     pa, vb[0], vb[1]);
                mma_f16(oacc[2*jp + 1], pa, vb[2], vb[3]);
            }
        }
    }

    // ---- final l reduction over the quad and store ----
    lsum0 += __shfl_xor_sync(0xffffffffu, lsum0, 1);
    lsum0 += __shfl_xor_sync(0xffffffffu, lsum0, 2);
    lsum1 += __shfl_xor_sync(0xffffffffu, lsum1, 1);
    lsum1 += __shfl_xor_sync(0xffffffffu, lsum1, 2);
    float inv0 = 1.f / lsum0;
    float inv1 = 1.f / lsum1;

    const int r0 = q0 + m0 + lq;
    const int r1 = r0 + 8;
    #pragma unroll
    for (int j = 0; j < 8; j++) {
        int c = h*HD_ + j*8 + 2*lr;
        float2 o0; o0.x = oacc[j][0]*inv0; o0.y = oacc[j][1]*inv0;
        float2 o1; o1.x = oacc[j][2]*inv1; o1.y = oacc[j][3]*inv1;
        *(float2*)(out + ((size_t)b*NQ_ + r0)*DM_ + c) = o0;
        *(float2*)(out + ((size_t)b*NQ_ + r1)*DM_ + c) = o1;
    }
}

// ---------------------------------------------------------------------------
extern "C" void kernel_launch(void* const* d_in, const int* in_sizes, int n_in,
                              void* d_out, int out_size)
{
    const float* q       = (const float*)d_in[0];
    const float* k       = (const float*)d_in[1];
    const float* v       = (const float*)d_in[2];
    const float* mask    = (const float*)d_in[3];
    const float* pearson = (const float*)d_in[4];
    const float* Wq      = (const float*)d_in[5];
    const float* bq      = (const float*)d_in[6];
    const float* Wk      = (const float*)d_in[7];
    const float* bk      = (const float*)d_in[8];
    const float* Wv      = (const float*)d_in[9];
    const float* bv      = (const float*)d_in[10];
    float* out = (float*)d_out;

    cudaFuncSetAttribute(proj_kernel,
                         cudaFuncAttributeMaxDynamicSharedMemorySize, PROJ_SMEM);
    cudaFuncSetAttribute(attn_kernel,
                         cudaFuncAttributeMaxDynamicSharedMemorySize, ATTN_SMEM);

    wcvt_kernel<<<768, 256>>>(Wq, Wk, Wv);
    diag_kernel<<<(B_*H_*NK_ + 255)/256, 256>>>(pearson);

    dim3 pg(DM_/128, (B_*NQ_)/128, 3);
    proj_kernel<<<pg, 512, PROJ_SMEM>>>(q, k, v, bq, bk, bv);

    dim3 ag(NQ_/128, H_, B_);
    attn_kernel<<<ag, 256, ATTN_SMEM>>>(mask, out);
}

// round 14
// speedup vs baseline: 1.8444x; 1.0849x over previous
#include <cuda_runtime.h>
#include <cuda_fp16.h>
#include <math.h>
#include <stdint.h>

#define B_   2
#define H_   8
#define NQ_  2048
#define NK_  2048
#define DM_  512
#define HD_  64
#define EXP2C 0.18033688011112042f   /* 0.125 * log2(e) */

#define SH2 36   // half2 words per 64-half row; 36%32==4 -> conflict-free frags
#define XF  40   // f32 words per 32-f32 row; conflict-free float2 frags
#define WS  20   // uint32 words per 32-half W row
#define MS  68   // f32 words per 64-f32 mask row; 68%32==4 -> <=2-way on float2

// Scratch (allocation-free rule: __device__ globals)
__device__ __half g_Q[B_*H_*NQ_*HD_];
__device__ __half g_K[B_*H_*NK_*HD_];
__device__ __half g_V[B_*H_*NK_*HD_];
__device__ __half g_Wh[3*DM_*DM_];
__device__ float  g_diag[B_*H_*NK_];

// ---------------------------------------------------------------------------
// helpers
// ---------------------------------------------------------------------------
__device__ __forceinline__ float fast_ex2(float x) {
    float y;
    asm("ex2.approx.ftz.f32 %0, %1;" : "=f"(y) : "f"(x));
    return y;
}
__device__ __forceinline__ uint32_t f2h2(float lo, float hi) {
    __half2 h = __floats2half2_rn(lo, hi);
    return *reinterpret_cast<uint32_t*>(&h);
}
__device__ __forceinline__ uint32_t ldsf2h(const float* p) {
    float2 v = *(const float2*)p;
    return f2h2(v.x, v.y);
}
__device__ __forceinline__ void mma_f16(float c[4], const uint32_t a[4],
                                        uint32_t b0, uint32_t b1) {
    asm volatile(
        "mma.sync.aligned.m16n8k16.row.col.f32.f16.f16.f32 "
        "{%0,%1,%2,%3}, {%4,%5,%6,%7}, {%8,%9}, {%0,%1,%2,%3};\n"
        : "+f"(c[0]), "+f"(c[1]), "+f"(c[2]), "+f"(c[3])
        : "r"(a[0]), "r"(a[1]), "r"(a[2]), "r"(a[3]), "r"(b0), "r"(b1));
}
__device__ __forceinline__ void ldsm_x4_t(uint32_t r[4], uint32_t addr) {
    asm volatile(
        "ldmatrix.sync.aligned.m8n8.x4.trans.shared.b16 {%0,%1,%2,%3}, [%4];"
        : "=r"(r[0]), "=r"(r[1]), "=r"(r[2]), "=r"(r[3]) : "r"(addr));
}
__device__ __forceinline__ uint32_t smem_u32(const void* p) {
    uint32_t a;
    asm("{ .reg .u64 t; cvta.to.shared.u64 t, %1; cvt.u32.u64 %0, t; }"
        : "=r"(a) : "l"(p));
    return a;
}
#define CPASYNC16(dst, src) \
    asm volatile("cp.async.cg.shared.global [%0], [%1], 16;" :: "r"(dst), "l"(src))
#define CPCOMMIT()  asm volatile("cp.async.commit_group;" ::: "memory")
#define CPWAIT0()   asm volatile("cp.async.wait_group 0;"  ::: "memory")
#define CPWAIT1()   asm volatile("cp.async.wait_group 1;"  ::: "memory")

// ---------------------------------------------------------------------------
// W fp32 -> fp16 pre-convert
// ---------------------------------------------------------------------------
__global__ void wcvt_kernel(const float* __restrict__ Wq,
                            const float* __restrict__ Wk,
                            const float* __restrict__ Wv)
{
    int idx = blockIdx.x * 256 + threadIdx.x;        // 0 .. 196607 (float4)
    const float* src = (idx < 65536) ? Wq : (idx < 131072 ? Wk : Wv);
    float4 w = *(const float4*)(src + (size_t)(idx & 65535) * 4);
    uint2 o;
    o.x = f2h2(w.x, w.y);
    o.y = f2h2(w.z, w.w);
    *(uint2*)(g_Wh + (size_t)idx * 4) = o;
}

// ---------------------------------------------------------------------------
// Projection (R12 proven): fp16 m16n8k16, cp.async double-buffered, 512 thr.
// ---------------------------------------------------------------------------
#define PROJ_SMEM (15360 * 4)

__global__ __launch_bounds__(512) void proj_kernel(
    const float* __restrict__ q, const float* __restrict__ k,
    const float* __restrict__ v,
    const float* __restrict__ bq, const float* __restrict__ bk,
    const float* __restrict__ bv)
{
    extern __shared__ float smf[];
    uint32_t* smu = (uint32_t*)smf;
    const uint32_t sb = smem_u32(smf);

    const float *X, *bias;
    const __half* Wh;
    __half* outp;
    if (blockIdx.z == 0)      { X = q; bias = bq; Wh = g_Wh;              outp = g_Q; }
    else if (blockIdx.z == 1) { X = k; bias = bk; Wh = g_Wh + DM_*DM_;    outp = g_K; }
    else                      { X = v; bias = bv; Wh = g_Wh + 2*DM_*DM_;  outp = g_V; }

    const int tid  = threadIdx.x;
    const int lane = tid & 31, warp = tid >> 5;
    const int lq = lane >> 2, lr = lane & 3;
    const int m0 = (warp & 7) * 16;
    const int n0 = (warp >> 3) * 64;
    const int row0 = blockIdx.y * 128;
    const int col0 = blockIdx.x * 128;

    const int sr = tid >> 3;
    const int sc = (tid & 7) << 2;
    const int wr = tid >> 2;
    const int wg = (tid & 3) << 3;

    float acc[8][4];
    #pragma unroll
    for (int j = 0; j < 8; j++)
        #pragma unroll
        for (int i = 0; i < 4; i++) acc[j][i] = 0.f;

    {
        #pragma unroll
        for (int it = 0; it < 2; it++) {
            int r = sr + it*64;
            CPASYNC16(sb + (uint32_t)((r*XF + sc) * 4),
                      X + (size_t)(row0 + r) * DM_ + sc);
        }
        CPASYNC16(sb + (uint32_t)((10240 + wr*WS) * 4 + wg*2),
                  Wh + (size_t)(col0 + wr) * DM_ + wg);
        CPCOMMIT();
    }

    int p = 0;
    for (int c = 0; c < 16; c++) {
        CPWAIT0();
        __syncthreads();
        if (c < 15) {
            #pragma unroll
            for (int it = 0; it < 2; it++) {
                int r = sr + it*64;
                CPASYNC16(sb + (uint32_t)((((p^1)*5120) + r*XF + sc) * 4),
                          X + (size_t)(row0 + r) * DM_ + (c+1)*32 + sc);
            }
            CPASYNC16(sb + (uint32_t)((10240 + (p^1)*2560 + wr*WS) * 4 + wg*2),
                      Wh + (size_t)(col0 + wr) * DM_ + (c+1)*32 + wg);
            CPCOMMIT();
        }

        const float*    Xp = smf + p*5120;
        const uint32_t* Wp = smu + 10240 + p*2560;

        #pragma unroll
        for (int kk = 0; kk < 2; kk++) {
            uint32_t a[4];
            const float* xb = Xp + (m0 + lq)*XF + kk*16 + 2*lr;
            a[0] = ldsf2h(xb);
            a[1] = ldsf2h(xb + 8*XF);
            a[2] = ldsf2h(xb + 8);
            a[3] = ldsf2h(xb + 8*XF + 8);
            #pragma unroll
            for (int j = 0; j < 8; j++) {
                const uint32_t* wb = Wp + (n0 + j*8 + lq)*WS + kk*8 + lr;
                mma_f16(acc[j], a, wb[0], wb[4]);
            }
        }
        p ^= 1;
    }

    const int r0g = row0 + m0 + lq;
    const int r1g = r0g + 8;
    #pragma unroll
    for (int j = 0; j < 8; j++) {
        int jj = col0 + n0 + j*8 + 2*lr;
        float2 bs = *(const float2*)(bias + jj);
        int h = jj >> 6, d = jj & 63;
        {
            int b = r0g >> 11, n = r0g & 2047;
            uint32_t o = f2h2(acc[j][0] + bs.x, acc[j][1] + bs.y);
            *(uint32_t*)(outp + (((size_t)(b*H_ + h) * NQ_) + n) * HD_ + d) = o;
        }
        {
            int b = r1g >> 11, n = r1g & 2047;
            uint32_t o = f2h2(acc[j][2] + bs.x, acc[j][3] + bs.y);
            *(uint32_t*)(outp + (((size_t)(b*H_ + h) * NQ_) + n) * HD_ + d) = o;
        }
    }
}

// ---------------------------------------------------------------------------
// diag extraction
// ---------------------------------------------------------------------------
__global__ void diag_kernel(const float* __restrict__ pearson)
{
    int idx = blockIdx.x * 256 + threadIdx.x;
    if (idx < B_*H_*NK_) {
        int k  = idx & (NK_ - 1);
        int bh = idx >> 11;
        g_diag[idx] = pearson[((size_t)bh * NK_ + k) * NK_ + k];
    }
}

// ---------------------------------------------------------------------------
// Fused attention, fully cp.async-pipelined (K/V/diag/mask all prefetched
// one tile ahead, double-buffered), P register-resident (C-frag of S == A-frag
// for PV, so no smem round trip for P).
// 256 threads (8 warps), 128 q-rows per CTA; 64-key tiles.
// smem words: KV[2]@0/4608 (Ks 2304 + Vs 2304 each), ds[2]@9216 (64 each),
//             mask[2]@9344/18048 (8704 each) -> 26752 words = 107008 B.
// Regs cap residency at 2 CTAs/SM; 2x107KB = 214KB smem fits -> no occ cost.
// grid (NQ/128, H, B)
// ---------------------------------------------------------------------------
#define KVS  4608
#define DS0  9216
#define MB0  9344
#define MB1  18048
#define ATTN_SMEM (26752 * 4)

__global__ __launch_bounds__(256) void attn_kernel(
    const float* __restrict__ mask, float* __restrict__ out)
{
    extern __shared__ uint32_t smu[];
    const uint32_t sb = smem_u32(smu);

    const int tid  = threadIdx.x;
    const int lane = tid & 31, warp = tid >> 5;
    const int lq = lane >> 2, lr = lane & 3;
    const int m0 = warp * 16;
    const int q0 = blockIdx.x * 128;
    const int h  = blockIdx.y;
    const int b  = blockIdx.z;
    const int bh = b * H_ + h;

    const __half* Qg = g_Q + (size_t)bh * NQ_ * HD_ + (size_t)q0 * HD_;
    const __half* Kg = g_K + (size_t)bh * NK_ * HD_;
    const __half* Vg = g_V + (size_t)bh * NK_ * HD_;
    const float*  dg = g_diag + (size_t)bh * NK_;
    const float*  mg = mask + ((size_t)bh * NQ_ + q0) * NK_;

    // staging coords
    const int sr  = tid >> 3;          // K/V rows 0..31, r = sr + it*32
    const int sc8 = (tid & 7) << 3;    // half col 0,8,..56
    const int msr = tid >> 4;          // mask rows 0..15, r = msr + it*16
    const int msc = (tid & 15) << 2;   // f32 col 0,4,..60

    // ---- stage Q into the MB0 area (scratch before mask uses it) ----
    #pragma unroll
    for (int it = 0; it < 4; it++) {
        int e = it*256 + tid;
        int r = e >> 3, c8 = (e & 7) << 3;
        *(uint4*)&smu[MB0 + r*SH2 + (c8 >> 1)] = *(const uint4*)(Qg + (size_t)r * HD_ + c8);
    }
    __syncthreads();

    uint32_t qf[4][4];
    #pragma unroll
    for (int kk = 0; kk < 4; kk++) {
        int ab = MB0 + (m0 + lq)*SH2 + kk*8 + lr;
        qf[kk][0] = smu[ab];
        qf[kk][1] = smu[ab + 8*SH2];
        qf[kk][2] = smu[ab + 4];
        qf[kk][3] = smu[ab + 8*SH2 + 4];
    }
    __syncthreads();   // everyone done reading MB0 before cp.async overwrites

    const uint32_t vs_lane = (uint32_t)(lane & 15) * (SH2*4)
                           + (uint32_t)(lane >> 4) * 16;

    float lsum0 = 0.f, lsum1 = 0.f;
    float oacc[8][4];
    #pragma unroll
    for (int j = 0; j < 8; j++)
        #pragma unroll
        for (int i = 0; i < 4; i++) oacc[j][i] = 0.f;

    // ---- prologue: group 0 = tile 0 (K/V/diag/mask) into parity 0 ----
    {
        #pragma unroll
        for (int it = 0; it < 2; it++) {
            int r = sr + it*32;
            CPASYNC16(sb + (uint32_t)((r*SH2 + (sc8>>1)) * 4),
                      Kg + (size_t)r * HD_ + sc8);
            CPASYNC16(sb + (uint32_t)((2304 + r*SH2 + (sc8>>1)) * 4),
                      Vg + (size_t)r * HD_ + sc8);
        }
        if (tid < 16)
            CPASYNC16(sb + (uint32_t)((DS0 + tid*4) * 4), dg + tid*4);
        #pragma unroll
        for (int it = 0; it < 8; it++) {
            int r = msr + it*16;
            CPASYNC16(sb + (uint32_t)((MB0 + r*MS + msc) * 4),
                      mg + (size_t)r * NK_ + msc);
        }
        CPCOMMIT();
    }

    for (int kt = 0; kt < NK_/64; kt++) {
        const int p = kt & 1;
        __syncthreads();   // all warps done reading parity p^1 buffers

        if (kt < NK_/64 - 1) {
            const int q2 = p ^ 1;
            const __half* Kt = Kg + (size_t)(kt+1) * 64 * HD_;
            const __half* Vt = Vg + (size_t)(kt+1) * 64 * HD_;
            const float*  mn = mg + (size_t)(kt+1) * 64;
            #pragma unroll
            for (int it = 0; it < 2; it++) {
                int r = sr + it*32;
                CPASYNC16(sb + (uint32_t)((q2*KVS + r*SH2 + (sc8>>1)) * 4),
                          Kt + (size_t)r * HD_ + sc8);
                CPASYNC16(sb + (uint32_t)((q2*KVS + 2304 + r*SH2 + (sc8>>1)) * 4),
                          Vt + (size_t)r * HD_ + sc8);
            }
            if (tid < 16)
                CPASYNC16(sb + (uint32_t)((DS0 + q2*64 + tid*4) * 4),
                          dg + (size_t)(kt+1)*64 + tid*4);
            #pragma unroll
            for (int it = 0; it < 8; it++) {
                int r = msr + it*16;
                CPASYNC16(sb + (uint32_t)(((q2 ? MB1 : MB0) + r*MS + msc) * 4),
                          mn + (size_t)r * NK_ + msc);
            }
            CPCOMMIT();
            CPWAIT1();      // current tile's group arrived; next stays in flight
        } else {
            CPWAIT0();
        }
        __syncthreads();

        const uint32_t* Ksp = smu + p*KVS;
        const uint32_t  vsb = sb + (uint32_t)((p*KVS + 2304) * 4) + vs_lane;
        const float*    dsp = (const float*)(smu + DS0 + p*64);
        const float*    msk = (const float*)(smu + (p ? MB1 : MB0));

        // ---- S = Q @ K^T ----
        float sacc[8][4];
        #pragma unroll
        for (int j = 0; j < 8; j++)
            #pragma unroll
            for (int i = 0; i < 4; i++) sacc[j][i] = 0.f;

        #pragma unroll
        for (int kk = 0; kk < 4; kk++) {
            #pragma unroll
            for (int j = 0; j < 8; j++) {
                int bb = (j*8 + lq)*SH2 + kk*8 + lr;
                mma_f16(sacc[j], qf[kk], Ksp[bb], Ksp[bb + 4]);
            }
        }

        // ---- fixed-base softmax + mask(smem)*diag, P stays in registers ----
        const float* mp0 = msk + (m0 + lq)*MS + 2*lr;
        const float* mp1 = mp0 + 8*MS;
        #pragma unroll
        for (int j = 0; j < 8; j++) {
            float2 mk0 = *(const float2*)(mp0 + j*8);
            float2 mk1 = *(const float2*)(mp1 + j*8);
            float2 d2  = *(const float2*)(dsp + j*8 + 2*lr);
            float p0 = fast_ex2(sacc[j][0] * EXP2C);
            float p1 = fast_ex2(sacc[j][1] * EXP2C);
            float p2 = fast_ex2(sacc[j][2] * EXP2C);
            float p3 = fast_ex2(sacc[j][3] * EXP2C);
            lsum0 += p0 + p1;
            lsum1 += p2 + p3;
            sacc[j][0] = p0 * mk0.x * d2.x;
            sacc[j][1] = p1 * mk0.y * d2.y;
            sacc[j][2] = p2 * mk1.x * d2.x;
            sacc[j][3] = p3 * mk1.y * d2.y;
        }

        // ---- O += P @ V  (A-frags packed directly from C-frags of S) ----
        #pragma unroll
        for (int kk = 0; kk < 4; kk++) {
            uint32_t pa[4];
            pa[0] = f2h2(sacc[2*kk][0],   sacc[2*kk][1]);
            pa[1] = f2h2(sacc[2*kk][2],   sacc[2*kk][3]);
            pa[2] = f2h2(sacc[2*kk+1][0], sacc[2*kk+1][1]);
            pa[3] = f2h2(sacc[2*kk+1][2], sacc[2*kk+1][3]);
            #pragma unroll
            for (int jp = 0; jp < 4; jp++) {
                uint32_t vb[4];
                ldsm_x4_t(vb, vsb + (uint32_t)kk*(16*SH2*4) + (uint32_t)jp*32);
                mma_f16(oacc[2*jp],     pa, vb[0], vb[1]);
                mma_f16(oacc[2*jp + 1], pa, vb[2], vb[3]);
            }
        }
    }

    // ---- final l reduction over the quad and store ----
    lsum0 += __shfl_xor_sync(0xffffffffu, lsum0, 1);
    lsum0 += __shfl_xor_sync(0xffffffffu, lsum0, 2);
    lsum1 += __shfl_xor_sync(0xffffffffu, lsum1, 1);
    lsum1 += __shfl_xor_sync(0xffffffffu, lsum1, 2);
    float inv0 = 1.f / lsum0;
    float inv1 = 1.f / lsum1;

    const int r0 = q0 + m0 + lq;
    const int r1 = r0 + 8;
    #pragma unroll
    for (int j = 0; j < 8; j++) {
        int c = h*HD_ + j*8 + 2*lr;
        float2 o0; o0.x = oacc[j][0]*inv0; o0.y = oacc[j][1]*inv0;
        float2 o1; o1.x = oacc[j][2]*inv1; o1.y = oacc[j][3]*inv1;
        *(float2*)(out + ((size_t)b*NQ_ + r0)*DM_ + c) = o0;
        *(float2*)(out + ((size_t)b*NQ_ + r1)*DM_ + c) = o1;
    }
}

// ---------------------------------------------------------------------------
extern "C" void kernel_launch(void* const* d_in, const int* in_sizes, int n_in,
                              void* d_out, int out_size)
{
    const float* q       = (const float*)d_in[0];
    const float* k       = (const float*)d_in[1];
    const float* v       = (const float*)d_in[2];
    const float* mask    = (const float*)d_in[3];
    const float* pearson = (const float*)d_in[4];
    const float* Wq      = (const float*)d_in[5];
    const float* bq      = (const float*)d_in[6];
    const float* Wk      = (const float*)d_in[7];
    const float* bk      = (const float*)d_in[8];
    const float* Wv      = (const float*)d_in[9];
    const float* bv      = (const float*)d_in[10];
    float* out = (float*)d_out;

    cudaFuncSetAttribute(proj_kernel,
                         cudaFuncAttributeMaxDynamicSharedMemorySize, PROJ_SMEM);
    cudaFuncSetAttribute(attn_kernel,
                         cudaFuncAttributeMaxDynamicSharedMemorySize, ATTN_SMEM);

    wcvt_kernel<<<768, 256>>>(Wq, Wk, Wv);
    diag_kernel<<<(B_*H_*NK_ + 255)/256, 256>>>(pearson);

    dim3 pg(DM_/128, (B_*NQ_)/128, 3);
    proj_kernel<<<pg, 512, PROJ_SMEM>>>(q, k, v, bq, bk, bv);

    dim3 ag(NQ_/128, H_, B_);
    attn_kernel<<<ag, 256, ATTN_SMEM>>>(mask, out);
}